// round 4
// baseline (speedup 1.0000x reference)
#include <cuda_runtime.h>
#include <math_constants.h>

// Problem constants (fixed shapes for this problem instance)
#define NEWN 65536      // new (coarse) nodes
#define BB   4          // batch
#define VV   64         // feature dim
#define BVN  256        // BB*VV fused columns
#define SPB  32         // segments handled per block

// Scratch: segment start offsets (row is sorted, every segment non-empty)
__device__ int g_seg_start[NEWN + 1];

// ---------------------------------------------------------------------------
// Kernel 1: segment boundaries from sorted row[]
// ---------------------------------------------------------------------------
__global__ void build_starts_kernel(const int* __restrict__ row, int nnz) {
    int i = blockIdx.x * blockDim.x + threadIdx.x;
    if (i >= nnz) return;
    int r = row[i];
    if (i == 0) {
        g_seg_start[r] = 0;
    } else {
        int rp = __ldg(row + i - 1);
        if (r != rp) g_seg_start[r] = i;
    }
    if (i == nnz - 1) g_seg_start[NEWN] = nnz;
}

// ---------------------------------------------------------------------------
// Kernel 2: per-segment weighted argmax pool + transposed index emit
//
// Thread t owns column j = v*BB + b  with  b = t>>6, v = t&63, so that the
// per-child x gather x[b, node, v] is warp-contiguous (128B per warp).
// Each block handles SPB consecutive segments; argmax node ids are staged in
// smem and written out transposed ([BV, new] layout) with coalesced 128B
// stores.
// ---------------------------------------------------------------------------
__global__ __launch_bounds__(256)
void pool_kernel(const float* __restrict__ x,
                 const float* __restrict__ weights,
                 const int*   __restrict__ col,
                 float* __restrict__ out,
                 int oldN,
                 int write_idx) {
    __shared__ int   s_node[BVN * SPB];   // [j][m_local] argmax node ids (32 KiB)
    __shared__ int   s_start[SPB + 1];
    __shared__ float s_w[SPB];

    const int t  = threadIdx.x;
    const int b  = t >> 6;
    const int v  = t & 63;
    const int j  = v * BB + b;
    const int m0 = blockIdx.x * SPB;

    if (t <= SPB) s_start[t] = g_seg_start[m0 + t];
    if (t < SPB)  s_w[t] = __ldg(weights + g_seg_start[m0 + t]);
    __syncthreads();

    // base pointer for this thread's (b, v) slice of x
    const float* xb = x + (size_t)b * oldN * VV + v;

    #pragma unroll 4
    for (int ml = 0; ml < SPB; ++ml) {
        const int   s = s_start[ml];
        const int   e = s_start[ml + 1];
        const float w = s_w[ml];

        float best_wv  = -CUDART_INF_F;
        float best_val = 0.0f;
        int   best_node = 0;

        for (int i = s; i < e; ++i) {
            int   node = __ldg(col + i);                     // uniform, L1-broadcast
            float val  = __ldg(xb + (size_t)node * VV);      // coalesced per warp
            float wv   = w * val;                            // matches reference fp32 mul
            if (wv > best_wv) {                              // strict > == min-index tiebreak
                best_wv = wv; best_val = val; best_node = node;
            }
        }

        const int m = m0 + ml;
        // x_pooled[b, m, v]  -- 128B coalesced per warp
        out[((size_t)b * NEWN + m) * VV + v] = best_val;
        s_node[j * SPB + ml] = best_node;
    }

    if (!write_idx) return;
    __syncthreads();

    // nnz_ind[0] at [j*NEWN + m] and nnz_ind[1] = j at the same offset in
    // the second region. Lanes write 32 consecutive m -> 128B stores.
    float* out1 = out  + (size_t)BB  * NEWN * VV;   // +16,777,216
    float* out2 = out1 + (size_t)BVN * NEWN;        // +16,777,216

    const int warp = t >> 5, lane = t & 31;
    #pragma unroll
    for (int jc = 0; jc < BVN / 8; ++jc) {
        const int jj   = jc * 8 + warp;
        const int node = s_node[jj * SPB + lane];   // stride-1 lanes: conflict-free
        const size_t off = (size_t)jj * NEWN + m0 + lane;
        out1[off] = (float)node;   // exact: node < 2^24
        out2[off] = (float)jj;
    }
}

// ---------------------------------------------------------------------------
// Launch
// inputs (metadata order): x f32[B,OLD,V], weights f32[nnz], row i32[nnz],
//                          col i32[nnz], new_nodes i32[1]
// output: concat(x_pooled f32[B,NEWN,V], nnz_ind[2, BV*NEWN])
// ---------------------------------------------------------------------------
extern "C" void kernel_launch(void* const* d_in, const int* in_sizes, int n_in,
                              void* d_out, int out_size) {
    const float* x       = (const float*)d_in[0];
    const float* weights = (const float*)d_in[1];
    const int*   row     = (const int*)d_in[2];
    const int*   col     = (const int*)d_in[3];

    const int nnz  = in_sizes[3];
    const int oldN = in_sizes[0] / (BB * VV);

    build_starts_kernel<<<(nnz + 255) / 256, 256>>>(row, nnz);

    const int pooled_elems = BB * NEWN * VV;                 // 16,777,216
    const int write_idx    = (out_size >= 3 * pooled_elems) ? 1 : 0;

    pool_kernel<<<NEWN / SPB, 256>>>(x, weights, col, (float*)d_out,
                                     oldN, write_idx);
}